// round 7
// baseline (speedup 1.0000x reference)
#include <cuda_runtime.h>
#include <cstdint>

// Problem constants
constexpr int Bb   = 64;
constexpr int IC   = 32;
constexpr int PC   = 128;
constexpr int RC   = 32;
constexpr int OC   = 128;
constexpr int Hh   = 96;
constexpr int Ww   = 320;
constexpr int Npts = 2048;
constexpr float EPS = 1e-5f;

constexpr int TILE    = 64;                 // points per block
constexpr int THREADS = 256;
constexpr int TILES_PER_B = Npts / TILE;    // 32
constexpr int GRID = Bb * TILES_PER_B;      // 2048

// ---------------- SMEM layout (floats) ----------------
// s_cat : [256][64]  rows 0..127 = pf, rows 128..255 = img_new (phase 4)
// s_img : [32][64]
// s_att : [64]
// Overlays inside s_cat's img_new half (free until phase 4):
//   gx  @ float 8192, gy @ 8256, atp @ 8320 (8 x 65)
constexpr int OFF_CAT = 0;
constexpr int OFF_IMG = 2 * PC * TILE;            // 16384
constexpr int OFF_ATT = OFF_IMG + IC * TILE;      // 18432
constexpr int SMEM_FLOATS = OFF_ATT + TILE;       // 18496
constexpr int SMEM_BYTES  = SMEM_FLOATS * 4;      // 73984 B -> 3 CTAs/SM
constexpr int OFF_GX  = 8192;                     // overlay
constexpr int OFF_GY  = 8256;
constexpr int OFF_ATP = 8320;                     // stride 65

// Prepped (transposed / folded) parameters in device scratch
__device__ __align__(16) float d_WfuseT[2 * PC * OC];  // [k=256][oc=128]
__device__ __align__(16) float d_WiaT[IC * PC];        // [k=32][oc=128]
__device__ __align__(16) float d_sc1[PC], d_sh1[PC], d_sc2[OC], d_sh2[OC];
__device__ __align__(16) float d_br[RC], d_w3[RC];
__device__ float d_b3[1];

#define DEV __device__ __forceinline__
typedef unsigned long long u64;

// ---- packed f32x2 helpers (Blackwell FFMA2) ----
DEV u64 pk2(float v) {
    u64 r;
    asm("mov.b64 %0, {%1, %1};" : "=l"(r) : "f"(v));
    return r;
}
DEV u64 f2fma(u64 a, u64 b, u64 c) {
    u64 d;
    asm("fma.rn.f32x2 %0, %1, %2, %3;" : "=l"(d) : "l"(a), "l"(b), "l"(c));
    return d;
}
DEV float2 upk(u64 a) {
    float2 f;
    asm("mov.b64 {%0, %1}, %2;" : "=f"(f.x), "=f"(f.y) : "l"(a));
    return f;
}
DEV float tanh_ap(float x) {
    float y;
    asm("tanh.approx.f32 %0, %1;" : "=f"(y) : "f"(x));
    return y;
}

// ---------------- prep: transposes + BN folding ----------------
__global__ void prep_kernel(const float* __restrict__ W_ia, const float* __restrict__ b_ia,
                            const float* __restrict__ g1, const float* __restrict__ bt1,
                            const float* __restrict__ m1, const float* __restrict__ v1,
                            const float* __restrict__ bf1, const float* __restrict__ bf2,
                            const float* __restrict__ Wf3, const float* __restrict__ bf3,
                            const float* __restrict__ W_fuse, const float* __restrict__ b_fuse,
                            const float* __restrict__ g2, const float* __restrict__ bt2,
                            const float* __restrict__ m2, const float* __restrict__ v2)
{
    int i = blockIdx.x * blockDim.x + threadIdx.x;
    if (i < 2 * PC * OC) { int k = i / OC, oc = i % OC; d_WfuseT[i] = W_fuse[oc * (2 * PC) + k]; }
    if (i < IC * PC)     { int k = i / PC, oc = i % PC; d_WiaT[i]   = W_ia[oc * IC + k]; }
    if (i < PC) {
        float s1 = g1[i] * rsqrtf(v1[i] + EPS);
        d_sc1[i] = s1;
        d_sh1[i] = (b_ia[i] - m1[i]) * s1 + bt1[i];
        float s2 = g2[i] * rsqrtf(v2[i] + EPS);
        d_sc2[i] = s2;
        d_sh2[i] = (b_fuse[i] - m2[i]) * s2 + bt2[i];
    }
    if (i < RC) { d_br[i] = bf1[i] + bf2[i]; d_w3[i] = Wf3[i]; }
    if (i == 0) d_b3[0] = bf3[0];
}

extern __shared__ float sm[];

__global__ void __launch_bounds__(THREADS, 3)
fused_rcnn_kernel(const float* __restrict__ img_map,   // (B,IC,H,W)
                  const float* __restrict__ xy,        // (B,N,2)
                  const float* __restrict__ pf,        // (B,PC,N)
                  const float* __restrict__ Wf1,       // (RC,IC)  [r][k]
                  const float* __restrict__ Wf2,       // (RC,PC)  [r][k]
                  float* __restrict__ out)             // (B,OC,N)
{
    const int tid = threadIdx.x;
    const int blk = blockIdx.x;
    const int b   = blk / TILES_PER_B;
    const int n0  = (blk % TILES_PER_B) * TILE;

    float* s_cat = sm + OFF_CAT;
    float* s_img = sm + OFF_IMG;
    float* s_att = sm + OFF_ATT;
    float* s_gx  = sm + OFF_GX;
    float* s_gy  = sm + OFF_GY;
    float* s_atp = sm + OFF_ATP;

    const int wid  = tid >> 5;
    const int lane = tid & 31;
    const int og   = lane & 3;     // oc / r sub-group
    const int pg   = lane >> 2;    // point group (8 pts)
    const int p8   = pg * 8;

    // ---------------- Phase 0: cooperative loads ----------------
    #pragma unroll
    for (int it = 0; it < 8; it++) {
        int i = tid + it * THREADS;              // 0..2047
        int c = i >> 4, q = i & 15;
        float4 v = __ldg((const float4*)(pf + (size_t)(b * PC + c) * Npts + n0) + q);
        *(float4*)(s_cat + c * TILE + q * 4) = v;
    }
    if (tid < TILE) {
        float2 p = __ldg((const float2*)xy + (size_t)b * Npts + n0 + tid);
        s_gx[tid] = ((p.x + 1.0f) * (float)Ww - 1.0f) * 0.5f;
        s_gy[tid] = ((p.y + 1.0f) * (float)Hh - 1.0f) * 0.5f;
    }
    __syncthreads();

    // ---------------- Phase 1: tap-cooperative bilinear gather ----------------
    // lane = (pt_local 0..7) * 4 + tap ; warp covers pts wid*8..wid*8+7, loops 32 channels
    {
        int ptl = lane >> 2, tap = lane & 3;
        int pt  = wid * 8 + ptl;
        float ix = s_gx[pt], iy = s_gy[pt];
        float fx0 = floorf(ix), fy0 = floorf(iy);
        int x0 = (int)fx0, y0 = (int)fy0;
        float wx1 = ix - fx0, wy1 = iy - fy0;
        int xt = x0 + (tap & 1);
        int yt = y0 + (tap >> 1);
        float wxt = (tap & 1) ? wx1 : 1.0f - wx1;
        float wyt = (tap >> 1) ? wy1 : 1.0f - wy1;
        bool valid = (xt >= 0) && (xt < Ww) && (yt >= 0) && (yt < Hh);
        float wt = valid ? wxt * wyt : 0.0f;
        int xc = min(max(xt, 0), Ww - 1);
        int yc = min(max(yt, 0), Hh - 1);
        const float* base = img_map + (size_t)(b * IC) * (Hh * Ww) + (size_t)yc * Ww + xc;
        #pragma unroll 4
        for (int c = 0; c < IC; c++) {
            float v = wt * __ldg(base + (size_t)c * (Hh * Ww));
            v += __shfl_xor_sync(0xffffffffu, v, 1);
            v += __shfl_xor_sync(0xffffffffu, v, 2);
            if (tap == 0) s_img[c * TILE + pt] = v;
        }
    }
    __syncthreads();

    // ---------------- Phase 2: attention GEMM (lane = 1 r x 8 pts) ----------------
    {
        const int r = wid * 4 + og;              // 0..31
        u64 a0 = 0, a1 = 0, a2 = 0, a3 = 0;
        #pragma unroll
        for (int k4 = 0; k4 < IC / 4; k4++) {
            float4 wv = __ldg((const float4*)(Wf1 + r * IC + k4 * 4));
            #pragma unroll
            for (int kk = 0; kk < 4; kk++) {
                const float* row = s_img + (k4 * 4 + kk) * TILE + p8;
                ulonglong2 c01 = *(const ulonglong2*)(row);
                ulonglong2 c23 = *(const ulonglong2*)(row + 4);
                u64 w = pk2(kk == 0 ? wv.x : kk == 1 ? wv.y : kk == 2 ? wv.z : wv.w);
                a0 = f2fma(w, c01.x, a0); a1 = f2fma(w, c01.y, a1);
                a2 = f2fma(w, c23.x, a2); a3 = f2fma(w, c23.y, a3);
            }
        }
        #pragma unroll 4
        for (int k4 = 0; k4 < PC / 4; k4++) {
            float4 wv = __ldg((const float4*)(Wf2 + r * PC + k4 * 4));
            #pragma unroll
            for (int kk = 0; kk < 4; kk++) {
                const float* row = s_cat + (k4 * 4 + kk) * TILE + p8;
                ulonglong2 c01 = *(const ulonglong2*)(row);
                ulonglong2 c23 = *(const ulonglong2*)(row + 4);
                u64 w = pk2(kk == 0 ? wv.x : kk == 1 ? wv.y : kk == 2 ? wv.z : wv.w);
                a0 = f2fma(w, c01.x, a0); a1 = f2fma(w, c01.y, a1);
                a2 = f2fma(w, c23.x, a2); a3 = f2fma(w, c23.y, a3);
            }
        }
        float br  = __ldg(d_br + r);
        float w3v = __ldg(d_w3 + r);
        float v[8];
        float2 t;
        t = upk(a0); v[0] = t.x; v[1] = t.y;
        t = upk(a1); v[2] = t.x; v[3] = t.y;
        t = upk(a2); v[4] = t.x; v[5] = t.y;
        t = upk(a3); v[6] = t.x; v[7] = t.y;
        #pragma unroll
        for (int j = 0; j < 8; j++) v[j] = tanh_ap(v[j] + br) * w3v;
        #pragma unroll
        for (int j = 0; j < 8; j++) {
            v[j] += __shfl_xor_sync(0xffffffffu, v[j], 1);
            v[j] += __shfl_xor_sync(0xffffffffu, v[j], 2);
        }
        if (og == 0) {
            #pragma unroll
            for (int j = 0; j < 8; j++) s_atp[wid * 65 + p8 + j] = v[j];
        }
    }
    __syncthreads();
    if (tid < TILE) {
        float s = d_b3[0];
        #pragma unroll
        for (int w = 0; w < 8; w++) s += s_atp[w * 65 + tid];
        s_att[tid] = 1.0f / (1.0f + __expf(-s));
    }
    __syncthreads();

    const int oc0 = wid * 16 + og * 4;           // this lane's 4 output channels

    // ---------------- Phase 4: img_new = relu(bn1(W_ia @ img)) * att ----------------
    // Two pt-halves of 4 pts each -> 8 u64 accumulators (register-lean for occ=3)
    #pragma unroll
    for (int hf = 0; hf < 2; hf++) {
        const int pb = p8 + hf * 4;
        u64 A[8];
        #pragma unroll
        for (int i = 0; i < 8; i++) A[i] = 0;
        #pragma unroll 4
        for (int k = 0; k < IC; k++) {
            float4 wv = __ldg((const float4*)(d_WiaT + k * PC + oc0));
            ulonglong2 c01 = *(const ulonglong2*)(s_img + k * TILE + pb);
            u64 w0 = pk2(wv.x), w1 = pk2(wv.y), w2 = pk2(wv.z), w3 = pk2(wv.w);
            A[0] = f2fma(w0, c01.x, A[0]); A[1] = f2fma(w0, c01.y, A[1]);
            A[2] = f2fma(w1, c01.x, A[2]); A[3] = f2fma(w1, c01.y, A[3]);
            A[4] = f2fma(w2, c01.x, A[4]); A[5] = f2fma(w2, c01.y, A[5]);
            A[6] = f2fma(w3, c01.x, A[6]); A[7] = f2fma(w3, c01.y, A[7]);
        }
        float4 at = *(const float4*)(s_att + pb);
        #pragma unroll
        for (int i = 0; i < 4; i++) {
            int oc = oc0 + i;
            float sc = __ldg(d_sc1 + oc), sh = __ldg(d_sh1 + oc);
            float2 q0 = upk(A[2 * i]), q1 = upk(A[2 * i + 1]);
            float4 o;
            o.x = fmaxf(q0.x * sc + sh, 0.f) * at.x;
            o.y = fmaxf(q0.y * sc + sh, 0.f) * at.y;
            o.z = fmaxf(q1.x * sc + sh, 0.f) * at.z;
            o.w = fmaxf(q1.y * sc + sh, 0.f) * at.w;
            *(float4*)(s_cat + (PC + oc) * TILE + pb) = o;
        }
    }
    __syncthreads();

    // ---------------- Phase 5: fuse GEMM (4 oc x 4 pts x 2 halves, k=256) ----------------
    #pragma unroll
    for (int hf = 0; hf < 2; hf++) {
        const int pb = p8 + hf * 4;
        u64 A[8];
        #pragma unroll
        for (int i = 0; i < 8; i++) A[i] = 0;
        #pragma unroll 4
        for (int k = 0; k < 2 * PC; k++) {
            float4 wv = __ldg((const float4*)(d_WfuseT + k * OC + oc0));
            ulonglong2 c01 = *(const ulonglong2*)(s_cat + k * TILE + pb);
            u64 w0 = pk2(wv.x), w1 = pk2(wv.y), w2 = pk2(wv.z), w3 = pk2(wv.w);
            A[0] = f2fma(w0, c01.x, A[0]); A[1] = f2fma(w0, c01.y, A[1]);
            A[2] = f2fma(w1, c01.x, A[2]); A[3] = f2fma(w1, c01.y, A[3]);
            A[4] = f2fma(w2, c01.x, A[4]); A[5] = f2fma(w2, c01.y, A[5]);
            A[6] = f2fma(w3, c01.x, A[6]); A[7] = f2fma(w3, c01.y, A[7]);
        }
        #pragma unroll
        for (int i = 0; i < 4; i++) {
            int oc = oc0 + i;
            float sc = __ldg(d_sc2 + oc), sh = __ldg(d_sh2 + oc);
            float2 q0 = upk(A[2 * i]), q1 = upk(A[2 * i + 1]);
            float4 o;
            o.x = fmaxf(q0.x * sc + sh, 0.f);
            o.y = fmaxf(q0.y * sc + sh, 0.f);
            o.z = fmaxf(q1.x * sc + sh, 0.f);
            o.w = fmaxf(q1.y * sc + sh, 0.f);
            *(float4*)(out + ((size_t)b * OC + oc) * Npts + n0 + pb) = o;
        }
    }
}

extern "C" void kernel_launch(void* const* d_in, const int* in_sizes, int n_in,
                              void* d_out, int out_size) {
    (void)in_sizes; (void)n_in; (void)out_size;
    const float* img_map = (const float*)d_in[0];
    const float* xy      = (const float*)d_in[1];
    const float* pf      = (const float*)d_in[2];
    const float* W_ia    = (const float*)d_in[3];
    const float* b_ia    = (const float*)d_in[4];
    const float* g1      = (const float*)d_in[5];
    const float* bt1     = (const float*)d_in[6];
    const float* m1      = (const float*)d_in[7];
    const float* v1      = (const float*)d_in[8];
    const float* Wf1     = (const float*)d_in[9];
    const float* bf1     = (const float*)d_in[10];
    const float* Wf2     = (const float*)d_in[11];
    const float* bf2     = (const float*)d_in[12];
    const float* Wf3     = (const float*)d_in[13];
    const float* bf3     = (const float*)d_in[14];
    const float* W_fuse  = (const float*)d_in[15];
    const float* b_fuse  = (const float*)d_in[16];
    const float* g2      = (const float*)d_in[17];
    const float* bt2     = (const float*)d_in[18];
    const float* m2      = (const float*)d_in[19];
    const float* v2      = (const float*)d_in[20];
    float* out = (float*)d_out;

    prep_kernel<<<(2 * PC * OC + 255) / 256, 256>>>(
        W_ia, b_ia, g1, bt1, m1, v1, bf1, bf2, Wf3, bf3,
        W_fuse, b_fuse, g2, bt2, m2, v2);

    cudaFuncSetAttribute(fused_rcnn_kernel,
                         cudaFuncAttributeMaxDynamicSharedMemorySize, SMEM_BYTES);
    fused_rcnn_kernel<<<GRID, THREADS, SMEM_BYTES>>>(img_map, xy, pf, Wf1, Wf2, out);
}